// round 3
// baseline (speedup 1.0000x reference)
#include <cuda_runtime.h>
#include <math.h>

#define BSZ   2
#define TSEQ  2048
#define DMODEL 1024
#define NHEAD 16
#define DHEAD 64
#define MROWS (BSZ * TSEQ)   // 4096

// Scratch (allocation-free rule: __device__ globals)
__device__ float g_q[MROWS * DMODEL];
__device__ float g_k[MROWS * DMODEL];
__device__ float g_v[MROWS * DMODEL];
__device__ float g_attn[MROWS * DMODEL];

// ---------------------------------------------------------------------------
// GEMM: C[M,N] = A[M,K] @ W[N,K]^T + bias[N]
// M = 4096, N = K = 1024 (fixed). 128x128x16 tiles, 256 threads, 8x8 micro.
// ---------------------------------------------------------------------------
__global__ __launch_bounds__(256) void gemm_bias_kernel(
    const float* __restrict__ A, const float* __restrict__ W,
    const float* __restrict__ bias, float* __restrict__ C)
{
    const int BM = 128, BN = 128, BK = 16;
    __shared__ float As[BK][BM + 4];
    __shared__ float Ws[BK][BN + 4];

    const int tid = threadIdx.x;
    const int bm = blockIdx.y * BM;
    const int bn = blockIdx.x * BN;
    const int tm = (tid >> 4) << 3;   // 0..120
    const int tn = (tid & 15) << 3;   // 0..120

    float acc[8][8];
#pragma unroll
    for (int i = 0; i < 8; i++)
#pragma unroll
        for (int j = 0; j < 8; j++) acc[i][j] = 0.0f;

    for (int k0 = 0; k0 < DMODEL; k0 += BK) {
#pragma unroll
        for (int i = 0; i < 2; i++) {
            int v   = (tid << 1) + i;       // 0..511
            int row = v >> 2;               // 0..127
            int c4  = (v & 3) << 2;         // 0,4,8,12
            float4 a = *(const float4*)(A + (size_t)(bm + row) * DMODEL + k0 + c4);
            As[c4 + 0][row] = a.x; As[c4 + 1][row] = a.y;
            As[c4 + 2][row] = a.z; As[c4 + 3][row] = a.w;
            float4 w = *(const float4*)(W + (size_t)(bn + row) * DMODEL + k0 + c4);
            Ws[c4 + 0][row] = w.x; Ws[c4 + 1][row] = w.y;
            Ws[c4 + 2][row] = w.z; Ws[c4 + 3][row] = w.w;
        }
        __syncthreads();

#pragma unroll
        for (int k = 0; k < BK; k++) {
            float ra[8], rb[8];
#pragma unroll
            for (int i = 0; i < 8; i++) ra[i] = As[k][tm + i];
#pragma unroll
            for (int i = 0; i < 8; i++) rb[i] = Ws[k][tn + i];
#pragma unroll
            for (int i = 0; i < 8; i++)
#pragma unroll
                for (int j = 0; j < 8; j++) acc[i][j] += ra[i] * rb[j];
        }
        __syncthreads();
    }

#pragma unroll
    for (int i = 0; i < 8; i++) {
#pragma unroll
        for (int j4 = 0; j4 < 8; j4 += 4) {
            float4 r;
            r.x = acc[i][j4 + 0] + bias[bn + tn + j4 + 0];
            r.y = acc[i][j4 + 1] + bias[bn + tn + j4 + 1];
            r.z = acc[i][j4 + 2] + bias[bn + tn + j4 + 2];
            r.w = acc[i][j4 + 3] + bias[bn + tn + j4 + 3];
            *(float4*)(C + (size_t)(bm + tm + i) * DMODEL + bn + tn + j4) = r;
        }
    }
}

// ---------------------------------------------------------------------------
// Causal flash attention, split-row version.
// Grid: (T/64, H, B), 128 threads/block = 64 query rows x 2 halves.
// Thread (row, half): half owns 32 of the 64 head dims. Score partials are
// combined via shfl_xor(1) (partner = adjacent lane, same warp). Softmax
// state (m, l) is replicated per pair. Registers ~= q[32]+o[32]+misc < 128
// -> 4 blocks/SM (512 thr) instead of 256 -> 2x occupancy.
// ---------------------------------------------------------------------------
__global__ __launch_bounds__(128, 4) void attn_kernel(
    const float* __restrict__ Q, const float* __restrict__ K,
    const float* __restrict__ V, float* __restrict__ O)
{
    __shared__ float4 Ks4[64][16];   // 16 KB
    __shared__ float4 Vs4[64][16];   // 16 KB
    __shared__ float  Ss[64][64];    // 16 KB  [j][row]

    const int qt   = blockIdx.x;
    const int h    = blockIdx.y;
    const int b    = blockIdx.z;
    const int tid  = threadIdx.x;        // 0..127
    const int row  = tid >> 1;           // query row in tile, 0..63
    const int half = tid & 1;            // which 32-dim half
    const int qrow = qt * 64 + row;

    const size_t row_base = (size_t)(b * TSEQ + qrow) * DMODEL + h * DHEAD;
    const size_t half_off = row_base + half * 32;

    // This thread's 32-dim half of the query row.
    float q[32];
#pragma unroll
    for (int d4 = 0; d4 < 8; d4++) {
        float4 t = *(const float4*)(Q + half_off + d4 * 4);
        q[d4 * 4 + 0] = t.x; q[d4 * 4 + 1] = t.y;
        q[d4 * 4 + 2] = t.z; q[d4 * 4 + 3] = t.w;
    }

    float o[32];
#pragma unroll
    for (int d = 0; d < 32; d++) o[d] = 0.0f;
    float m = -1e30f, l = 0.0f;

    for (int kt = 0; kt <= qt; kt++) {
        __syncthreads();  // previous tile's smem fully consumed
        // Cooperative coalesced load of K and V tiles (64x64 floats each):
        // 1024 float4 per tile, 128 threads -> 8 float4 each per tensor.
        const float* Kbase = K + (size_t)(b * TSEQ + kt * 64) * DMODEL + h * DHEAD;
        const float* Vbase = V + (size_t)(b * TSEQ + kt * 64) * DMODEL + h * DHEAD;
#pragma unroll
        for (int i = 0; i < 8; i++) {
            int v  = i * 128 + tid;   // 0..1023
            int r  = v >> 4;          // 0..63
            int c4 = v & 15;          // 0..15
            Ks4[r][c4] = *(const float4*)(Kbase + (size_t)r * DMODEL + c4 * 4);
            Vs4[r][c4] = *(const float4*)(Vbase + (size_t)r * DMODEL + c4 * 4);
        }
        __syncthreads();

        const bool diag = (kt == qt);

        // Pass 1: scores. Each thread dots its 32-dim half, pairs combine.
        float tmax = -1e30f;
#pragma unroll 2
        for (int j = 0; j < 64; j++) {
            float a0 = 0.f, a1 = 0.f, a2 = 0.f, a3 = 0.f;
#pragma unroll
            for (int d4 = 0; d4 < 8; d4++) {
                float4 kv = Ks4[j][half * 8 + d4];
                a0 += q[d4 * 4 + 0] * kv.x;
                a1 += q[d4 * 4 + 1] * kv.y;
                a2 += q[d4 * 4 + 2] * kv.z;
                a3 += q[d4 * 4 + 3] * kv.w;
            }
            float part = (a0 + a1) + (a2 + a3);
            float s = part + __shfl_xor_sync(0xffffffffu, part, 1);
            s *= 0.125f;                          // 1/sqrt(64)
            if (diag && j > row) s = -1e30f;      // causal mask
            if (half == 0) Ss[j][row] = s;
            tmax = fmaxf(tmax, s);
        }

        // Online softmax update (replicated per pair, identical values).
        float mnew  = fmaxf(m, tmax);
        float alpha = __expf(m - mnew);
        l *= alpha;
#pragma unroll
        for (int d = 0; d < 32; d++) o[d] *= alpha;

        __syncthreads();  // Ss visible to both halves

        // Pass 2: P*V accumulation over this thread's 32-dim half.
#pragma unroll 2
        for (int j = 0; j < 64; j++) {
            float p = __expf(Ss[j][row] - mnew);
            l += p;
#pragma unroll
            for (int d4 = 0; d4 < 8; d4++) {
                float4 vv = Vs4[j][half * 8 + d4];
                o[d4 * 4 + 0] += p * vv.x;
                o[d4 * 4 + 1] += p * vv.y;
                o[d4 * 4 + 2] += p * vv.z;
                o[d4 * 4 + 3] += p * vv.w;
            }
        }
        m = mnew;
    }

    // Normalize and write this thread's half of the output row.
    float inv = 1.0f / l;
#pragma unroll
    for (int d4 = 0; d4 < 8; d4++) {
        float4 r;
        r.x = o[d4 * 4 + 0] * inv;
        r.y = o[d4 * 4 + 1] * inv;
        r.z = o[d4 * 4 + 2] * inv;
        r.w = o[d4 * 4 + 3] * inv;
        *(float4*)(O + half_off + d4 * 4) = r;
    }
}

// ---------------------------------------------------------------------------
extern "C" void kernel_launch(void* const* d_in, const int* in_sizes, int n_in,
                              void* d_out, int out_size)
{
    (void)in_sizes; (void)n_in; (void)out_size;
    const float* query = (const float*)d_in[0];
    const float* key_  = (const float*)d_in[1];
    const float* value = (const float*)d_in[2];
    const float* q_w   = (const float*)d_in[3];
    const float* q_b   = (const float*)d_in[4];
    const float* k_w   = (const float*)d_in[5];
    const float* k_b   = (const float*)d_in[6];
    const float* v_w   = (const float*)d_in[7];
    const float* v_b   = (const float*)d_in[8];
    const float* o_w   = (const float*)d_in[9];
    const float* o_b   = (const float*)d_in[10];
    float* out = (float*)d_out;

    float *qp, *kp, *vp, *ap;
    cudaGetSymbolAddress((void**)&qp, g_q);
    cudaGetSymbolAddress((void**)&kp, g_k);
    cudaGetSymbolAddress((void**)&vp, g_v);
    cudaGetSymbolAddress((void**)&ap, g_attn);

    dim3 ggrid(DMODEL / 128, MROWS / 128);   // (8, 32)
    gemm_bias_kernel<<<ggrid, 256>>>(query, q_w, q_b, qp);
    gemm_bias_kernel<<<ggrid, 256>>>(key_,  k_w, k_b, kp);
    gemm_bias_kernel<<<ggrid, 256>>>(value, v_w, v_b, vp);

    attn_kernel<<<dim3(TSEQ / 64, NHEAD, BSZ), 128>>>(qp, kp, vp, ap);

    gemm_bias_kernel<<<ggrid, 256>>>(ap, o_w, o_b, out);
}

// round 4
// speedup vs baseline: 1.4031x; 1.4031x over previous
#include <cuda_runtime.h>
#include <math.h>

#define BSZ   2
#define TSEQ  2048
#define DMODEL 1024
#define NHEAD 16
#define DHEAD 64
#define MROWS (BSZ * TSEQ)   // 4096

// Scratch (allocation-free rule: __device__ globals)
__device__ float g_q[MROWS * DMODEL];
__device__ float g_k[MROWS * DMODEL];
__device__ float g_v[MROWS * DMODEL];
__device__ float g_attn[MROWS * DMODEL];

// ---------------------------------------------------------------------------
// GEMM: C[M,N] = A[M,K] @ W[N,K]^T + bias[N]
// M = 4096, N = K = 1024 (fixed). 128x128x16 tiles, 256 threads, 8x8 micro.
// ---------------------------------------------------------------------------
__global__ __launch_bounds__(256) void gemm_bias_kernel(
    const float* __restrict__ A, const float* __restrict__ W,
    const float* __restrict__ bias, float* __restrict__ C)
{
    const int BM = 128, BN = 128, BK = 16;
    __shared__ float As[BK][BM + 4];
    __shared__ float Ws[BK][BN + 4];

    const int tid = threadIdx.x;
    const int bm = blockIdx.y * BM;
    const int bn = blockIdx.x * BN;
    const int tm = (tid >> 4) << 3;
    const int tn = (tid & 15) << 3;

    float acc[8][8];
#pragma unroll
    for (int i = 0; i < 8; i++)
#pragma unroll
        for (int j = 0; j < 8; j++) acc[i][j] = 0.0f;

    for (int k0 = 0; k0 < DMODEL; k0 += BK) {
#pragma unroll
        for (int i = 0; i < 2; i++) {
            int v   = (tid << 1) + i;
            int row = v >> 2;
            int c4  = (v & 3) << 2;
            float4 a = *(const float4*)(A + (size_t)(bm + row) * DMODEL + k0 + c4);
            As[c4 + 0][row] = a.x; As[c4 + 1][row] = a.y;
            As[c4 + 2][row] = a.z; As[c4 + 3][row] = a.w;
            float4 w = *(const float4*)(W + (size_t)(bn + row) * DMODEL + k0 + c4);
            Ws[c4 + 0][row] = w.x; Ws[c4 + 1][row] = w.y;
            Ws[c4 + 2][row] = w.z; Ws[c4 + 3][row] = w.w;
        }
        __syncthreads();

#pragma unroll
        for (int k = 0; k < BK; k++) {
            float ra[8], rb[8];
#pragma unroll
            for (int i = 0; i < 8; i++) ra[i] = As[k][tm + i];
#pragma unroll
            for (int i = 0; i < 8; i++) rb[i] = Ws[k][tn + i];
#pragma unroll
            for (int i = 0; i < 8; i++)
#pragma unroll
                for (int j = 0; j < 8; j++) acc[i][j] += ra[i] * rb[j];
        }
        __syncthreads();
    }

#pragma unroll
    for (int i = 0; i < 8; i++) {
#pragma unroll
        for (int j4 = 0; j4 < 8; j4 += 4) {
            float4 r;
            r.x = acc[i][j4 + 0] + bias[bn + tn + j4 + 0];
            r.y = acc[i][j4 + 1] + bias[bn + tn + j4 + 1];
            r.z = acc[i][j4 + 2] + bias[bn + tn + j4 + 2];
            r.w = acc[i][j4 + 3] + bias[bn + tn + j4 + 3];
            *(float4*)(C + (size_t)(bm + tm + i) * DMODEL + bn + tn + j4) = r;
        }
    }
}

// ---------------------------------------------------------------------------
// Causal flash attention, GEMM-style register tiling.
// Grid (T/128, H, B), 256 threads. Block: 128 queries x 64-key tiles.
// S = Q@K^T and O += P@V both as 8x4 register micro-tile GEMMs from smem.
// Softmax by 128 row-owner threads over the S tile in smem.
// ---------------------------------------------------------------------------
#define QS_STRIDE 132   // Qs[64][132]  (d, q)
#define KS_STRIDE 68    // Ks[64][68]   (d, k)
#define VS_STRIDE 68    // Vs[64][68]   (k, d)
#define PS_STRIDE 131   // Ps[64][131]  (k, q)  odd pad -> ~conflict-free xposed stores
#define QS_OFF 0
#define KS_OFF 8448
#define VS_OFF 12800
#define PS_OFF 17152
#define AUX_OFF 25536
#define ATTN_SMEM_FLOATS 25664
#define ATTN_SMEM_BYTES (ATTN_SMEM_FLOATS * 4)

__global__ __launch_bounds__(256, 2) void attn_kernel(
    const float* __restrict__ Q, const float* __restrict__ K,
    const float* __restrict__ V, float* __restrict__ O)
{
    extern __shared__ float sm[];
    float* Qs = sm + QS_OFF;
    float* Ks = sm + KS_OFF;
    float* Vs = sm + VS_OFF;
    float* Ps = sm + PS_OFF;
    float* rowAux = sm + AUX_OFF;   // alpha per tile, then 1/l at the end

    const int qt  = blockIdx.x;
    const int h   = blockIdx.y;
    const int b   = blockIdx.z;
    const int tid = threadIdx.x;
    const int q0  = qt * 128;
    const int tq  = (tid >> 4) << 3;   // 8 query rows
    const int tk  = (tid & 15) << 2;   // 4 keys (S phase) / 4 dims (O phase)

    // Load Q tile [128 x 64] transposed into Qs[d][q], pre-scaled by 1/sqrt(64).
    const float* Qg = Q + (size_t)(b * TSEQ + q0) * DMODEL + h * DHEAD;
#pragma unroll
    for (int i = 0; i < 8; i++) {
        int v  = i * 256 + tid;     // 0..2047
        int qr = v >> 4;            // 0..127
        int d4 = (v & 15) << 2;     // 0..60
        float4 t = *(const float4*)(Qg + (size_t)qr * DMODEL + d4);
        Qs[(d4 + 0) * QS_STRIDE + qr] = t.x * 0.125f;
        Qs[(d4 + 1) * QS_STRIDE + qr] = t.y * 0.125f;
        Qs[(d4 + 2) * QS_STRIDE + qr] = t.z * 0.125f;
        Qs[(d4 + 3) * QS_STRIDE + qr] = t.w * 0.125f;
    }

    float acc_o[8][4];
#pragma unroll
    for (int i = 0; i < 8; i++)
#pragma unroll
        for (int j = 0; j < 4; j++) acc_o[i][j] = 0.0f;

    float m = -1e30f, l = 0.0f;     // softmax state, owned by tid < 128

    const int n_kt = q0 / 64 + 2;
    for (int kt = 0; kt < n_kt; kt++) {
        __syncthreads();   // prior phase done with Ks/Vs/Ps

        // Load K tile (transposed -> Ks[d][k]) and V tile (natural -> Vs[k][d]).
        const float* Kg = K + (size_t)(b * TSEQ + kt * 64) * DMODEL + h * DHEAD;
        const float* Vg = V + (size_t)(b * TSEQ + kt * 64) * DMODEL + h * DHEAD;
#pragma unroll
        for (int i = 0; i < 4; i++) {
            int v  = i * 256 + tid;   // 0..1023
            int kr = v >> 4;          // 0..63
            int d4 = (v & 15) << 2;   // 0..60
            float4 t = *(const float4*)(Kg + (size_t)kr * DMODEL + d4);
            Ks[(d4 + 0) * KS_STRIDE + kr] = t.x;
            Ks[(d4 + 1) * KS_STRIDE + kr] = t.y;
            Ks[(d4 + 2) * KS_STRIDE + kr] = t.z;
            Ks[(d4 + 3) * KS_STRIDE + kr] = t.w;
            float4 u = *(const float4*)(Vg + (size_t)kr * DMODEL + d4);
            *(float4*)(Vs + kr * VS_STRIDE + d4) = u;
        }
        __syncthreads();

        // S = Q @ K^T : 8x4 micro-tile per thread.
        float accs[8][4];
#pragma unroll
        for (int i = 0; i < 8; i++)
#pragma unroll
            for (int j = 0; j < 4; j++) accs[i][j] = 0.0f;

#pragma unroll 4
        for (int d = 0; d < 64; d++) {
            float4 a0 = *(const float4*)(Qs + d * QS_STRIDE + tq);
            float4 a1 = *(const float4*)(Qs + d * QS_STRIDE + tq + 4);
            float4 bb = *(const float4*)(Ks + d * KS_STRIDE + tk);
            float av[8] = {a0.x, a0.y, a0.z, a0.w, a1.x, a1.y, a1.z, a1.w};
            float bv[4] = {bb.x, bb.y, bb.z, bb.w};
#pragma unroll
            for (int i = 0; i < 8; i++)
#pragma unroll
                for (int j = 0; j < 4; j++) accs[i][j] += av[i] * bv[j];
        }
        // Store transposed: Ps[k][q].
#pragma unroll
        for (int j = 0; j < 4; j++)
#pragma unroll
            for (int i = 0; i < 8; i++)
                Ps[(tk + j) * PS_STRIDE + tq + i] = accs[i][j];
        __syncthreads();

        // Row softmax (online). Thread r < 128 owns query row q0+r.
        if (tid < 128) {
            int qrow  = q0 + tid;
            int limit = qrow - kt * 64;          // valid keys: k <= limit
            if (limit > 63) limit = 63;
            float tmax = -1e30f;
            for (int k = 0; k <= limit; k++)
                tmax = fmaxf(tmax, Ps[k * PS_STRIDE + tid]);
            float mnew  = fmaxf(m, tmax);
            float alpha = __expf(m - mnew);
            float ls = 0.0f;
#pragma unroll 4
            for (int k = 0; k < 64; k++) {
                float p = (k <= limit) ? __expf(Ps[k * PS_STRIDE + tid] - mnew) : 0.0f;
                Ps[k * PS_STRIDE + tid] = p;
                ls += p;
            }
            l = l * alpha + ls;
            m = mnew;
            rowAux[tid] = alpha;
        }
        __syncthreads();

        // Rescale running O by alpha, then O += P @ V (8 rows x 4 dims).
#pragma unroll
        for (int i = 0; i < 8; i++) {
            float al = rowAux[tq + i];
#pragma unroll
            for (int j = 0; j < 4; j++) acc_o[i][j] *= al;
        }
#pragma unroll 4
        for (int kk = 0; kk < 64; kk++) {
            float4 vv = *(const float4*)(Vs + kk * VS_STRIDE + tk);
#pragma unroll
            for (int i = 0; i < 8; i++) {
                float p = Ps[kk * PS_STRIDE + tq + i];
                acc_o[i][0] += p * vv.x;
                acc_o[i][1] += p * vv.y;
                acc_o[i][2] += p * vv.z;
                acc_o[i][3] += p * vv.w;
            }
        }
    }

    __syncthreads();
    if (tid < 128) rowAux[tid] = 1.0f / l;
    __syncthreads();

    float* Og = O + (size_t)(b * TSEQ + q0) * DMODEL + h * DHEAD;
#pragma unroll
    for (int i = 0; i < 8; i++) {
        float inv = rowAux[tq + i];
        float4 r;
        r.x = acc_o[i][0] * inv;
        r.y = acc_o[i][1] * inv;
        r.z = acc_o[i][2] * inv;
        r.w = acc_o[i][3] * inv;
        *(float4*)(Og + (size_t)(tq + i) * DMODEL + tk) = r;
    }
}

// ---------------------------------------------------------------------------
extern "C" void kernel_launch(void* const* d_in, const int* in_sizes, int n_in,
                              void* d_out, int out_size)
{
    (void)in_sizes; (void)n_in; (void)out_size;
    const float* query = (const float*)d_in[0];
    const float* key_  = (const float*)d_in[1];
    const float* value = (const float*)d_in[2];
    const float* q_w   = (const float*)d_in[3];
    const float* q_b   = (const float*)d_in[4];
    const float* k_w   = (const float*)d_in[5];
    const float* k_b   = (const float*)d_in[6];
    const float* v_w   = (const float*)d_in[7];
    const float* v_b   = (const float*)d_in[8];
    const float* o_w   = (const float*)d_in[9];
    const float* o_b   = (const float*)d_in[10];
    float* out = (float*)d_out;

    float *qp, *kp, *vp, *ap;
    cudaGetSymbolAddress((void**)&qp, g_q);
    cudaGetSymbolAddress((void**)&kp, g_k);
    cudaGetSymbolAddress((void**)&vp, g_v);
    cudaGetSymbolAddress((void**)&ap, g_attn);

    static int attn_cfg = 0;
    if (!attn_cfg) {
        cudaFuncSetAttribute(attn_kernel,
                             cudaFuncAttributeMaxDynamicSharedMemorySize,
                             ATTN_SMEM_BYTES);
        attn_cfg = 1;
    }

    dim3 ggrid(DMODEL / 128, MROWS / 128);   // (8, 32)
    gemm_bias_kernel<<<ggrid, 256>>>(query, q_w, q_b, qp);
    gemm_bias_kernel<<<ggrid, 256>>>(key_,  k_w, k_b, kp);
    gemm_bias_kernel<<<ggrid, 256>>>(value, v_w, v_b, vp);

    attn_kernel<<<dim3(TSEQ / 128, NHEAD, BSZ), 256, ATTN_SMEM_BYTES>>>(qp, kp, vp, ap);

    gemm_bias_kernel<<<ggrid, 256>>>(ap, o_w, o_b, out);
}

// round 7
// speedup vs baseline: 2.3445x; 1.6709x over previous
#include <cuda_runtime.h>
#include <math.h>
#include <stdint.h>

#define BSZ   2
#define TSEQ  2048
#define DMODEL 1024
#define NHEAD 16
#define DHEAD 64
#define MROWS (BSZ * TSEQ)   // 4096

// Scratch (allocation-free rule: __device__ globals)
__device__ float g_q[MROWS * DMODEL];
__device__ float g_k[MROWS * DMODEL];
__device__ float g_v[MROWS * DMODEL];
__device__ float g_attn[MROWS * DMODEL];

__device__ __forceinline__ float tf32r(float x) {
    asm("cvt.rna.tf32.f32 %0, %0;" : "+f"(x));
    return x;
}

__device__ __forceinline__ void mma_tf32(float* c, const uint32_t* a, const uint32_t* b) {
    asm volatile(
        "mma.sync.aligned.m16n8k8.row.col.f32.tf32.tf32.f32 "
        "{%0,%1,%2,%3}, {%4,%5,%6,%7}, {%8,%9}, {%0,%1,%2,%3};"
        : "+f"(c[0]), "+f"(c[1]), "+f"(c[2]), "+f"(c[3])
        : "r"(a[0]), "r"(a[1]), "r"(a[2]), "r"(a[3]), "r"(b[0]), "r"(b[1]));
}

// ===========================================================================
// Tensor-core GEMM via legacy mma.sync (tf32): C = A[M,K] @ W[N,K]^T + bias
// M=4096, N=K=1024. 128x128 block tile, 8 warps (2x4), warp tile 64x32,
// m16n8k8 tf32. Smem [row][36] padding: STS.128 and all fragment LDS
// conflict-free (bank = 4*row + k distinct across warp).
// ===========================================================================
__global__ __launch_bounds__(256) void gemm_mma_kernel(
    const float* __restrict__ A, const float* __restrict__ W,
    const float* __restrict__ bias, float* __restrict__ C)
{
    __shared__ float As[128][36];
    __shared__ float Ws[128][36];

    const int tid = threadIdx.x;
    const int wid = tid >> 5;
    const int lid = tid & 31;
    const int bn  = blockIdx.x * 128;
    const int bm  = blockIdx.y * 128;
    const int wm  = (wid >> 2) * 64;    // warp tile m origin (0 / 64)
    const int wn  = (wid & 3) * 32;     // warp tile n origin (0/32/64/96)
    const int g   = lid >> 2;           // groupID 0..7
    const int tig = lid & 3;            // threadInGroup 0..3

    float acc[4][4][4];
#pragma unroll
    for (int mi = 0; mi < 4; mi++)
#pragma unroll
        for (int ni = 0; ni < 4; ni++)
#pragma unroll
            for (int r = 0; r < 4; r++) acc[mi][ni][r] = 0.0f;

    for (int k0 = 0; k0 < DMODEL; k0 += 32) {
        if (k0) __syncthreads();   // previous chunk's smem fully consumed
        // Coalesced loads: 128 rows x 32 cols per operand, natural layout.
#pragma unroll
        for (int i = 0; i < 4; i++) {
            int v   = i * 256 + tid;    // 0..1023
            int row = v >> 3;           // 0..127
            int c4  = (v & 7) << 2;     // 0..28
            float4 a = *(const float4*)(A + (size_t)(bm + row) * DMODEL + k0 + c4);
            a.x = tf32r(a.x); a.y = tf32r(a.y); a.z = tf32r(a.z); a.w = tf32r(a.w);
            *(float4*)&As[row][c4] = a;
            float4 w = *(const float4*)(W + (size_t)(bn + row) * DMODEL + k0 + c4);
            w.x = tf32r(w.x); w.y = tf32r(w.y); w.z = tf32r(w.z); w.w = tf32r(w.w);
            *(float4*)&Ws[row][c4] = w;
        }
        __syncthreads();

#pragma unroll
        for (int kk = 0; kk < 32; kk += 8) {
            uint32_t af[4][4], bf[4][2];
#pragma unroll
            for (int mi = 0; mi < 4; mi++) {
                const int m = wm + mi * 16 + g;
                af[mi][0] = __float_as_uint(As[m    ][kk + tig    ]);
                af[mi][1] = __float_as_uint(As[m + 8][kk + tig    ]);
                af[mi][2] = __float_as_uint(As[m    ][kk + tig + 4]);
                af[mi][3] = __float_as_uint(As[m + 8][kk + tig + 4]);
            }
#pragma unroll
            for (int ni = 0; ni < 4; ni++) {
                const int n = wn + ni * 8 + g;
                bf[ni][0] = __float_as_uint(Ws[n][kk + tig    ]);
                bf[ni][1] = __float_as_uint(Ws[n][kk + tig + 4]);
            }
#pragma unroll
            for (int mi = 0; mi < 4; mi++)
#pragma unroll
                for (int ni = 0; ni < 4; ni++)
                    mma_tf32(acc[mi][ni], af[mi], bf[ni]);
        }
    }

    // Epilogue: c0:(g, 2t) c1:(g, 2t+1) c2:(g+8, 2t) c3:(g+8, 2t+1)
#pragma unroll
    for (int ni = 0; ni < 4; ni++) {
        const int n = bn + wn + ni * 8 + 2 * tig;
        const float b0 = bias[n], b1 = bias[n + 1];
#pragma unroll
        for (int mi = 0; mi < 4; mi++) {
            const int m0 = bm + wm + mi * 16 + g;
            float2 lo = make_float2(acc[mi][ni][0] + b0, acc[mi][ni][1] + b1);
            float2 hi = make_float2(acc[mi][ni][2] + b0, acc[mi][ni][3] + b1);
            *(float2*)(C + (size_t)m0 * DMODEL + n)       = lo;
            *(float2*)(C + (size_t)(m0 + 8) * DMODEL + n) = hi;
        }
    }
}

// ---------------------------------------------------------------------------
// Causal flash attention, GEMM-style register tiling (unchanged, 695us).
// ---------------------------------------------------------------------------
#define QS_STRIDE 132
#define KS_STRIDE 68
#define VS_STRIDE 68
#define PS_STRIDE 131
#define QS_OFF 0
#define KS_OFF 8448
#define VS_OFF 12800
#define PS_OFF 17152
#define AUX_OFF 25536
#define ATTN_SMEM_FLOATS 25664
#define ATTN_SMEM_BYTES (ATTN_SMEM_FLOATS * 4)

__global__ __launch_bounds__(256, 2) void attn_kernel(
    const float* __restrict__ Q, const float* __restrict__ K,
    const float* __restrict__ V, float* __restrict__ O)
{
    extern __shared__ float sm[];
    float* Qs = sm + QS_OFF;
    float* Ks = sm + KS_OFF;
    float* Vs = sm + VS_OFF;
    float* Ps = sm + PS_OFF;
    float* rowAux = sm + AUX_OFF;

    const int qt  = blockIdx.x;
    const int h   = blockIdx.y;
    const int b   = blockIdx.z;
    const int tid = threadIdx.x;
    const int q0  = qt * 128;
    const int tq  = (tid >> 4) << 3;
    const int tk  = (tid & 15) << 2;

    const float* Qg = Q + (size_t)(b * TSEQ + q0) * DMODEL + h * DHEAD;
#pragma unroll
    for (int i = 0; i < 8; i++) {
        int v  = i * 256 + tid;
        int qr = v >> 4;
        int d4 = (v & 15) << 2;
        float4 t = *(const float4*)(Qg + (size_t)qr * DMODEL + d4);
        Qs[(d4 + 0) * QS_STRIDE + qr] = t.x * 0.125f;
        Qs[(d4 + 1) * QS_STRIDE + qr] = t.y * 0.125f;
        Qs[(d4 + 2) * QS_STRIDE + qr] = t.z * 0.125f;
        Qs[(d4 + 3) * QS_STRIDE + qr] = t.w * 0.125f;
    }

    float acc_o[8][4];
#pragma unroll
    for (int i = 0; i < 8; i++)
#pragma unroll
        for (int j = 0; j < 4; j++) acc_o[i][j] = 0.0f;

    float m = -1e30f, l = 0.0f;

    const int n_kt = q0 / 64 + 2;
    for (int kt = 0; kt < n_kt; kt++) {
        __syncthreads();
        const float* Kg = K + (size_t)(b * TSEQ + kt * 64) * DMODEL + h * DHEAD;
        const float* Vg = V + (size_t)(b * TSEQ + kt * 64) * DMODEL + h * DHEAD;
#pragma unroll
        for (int i = 0; i < 4; i++) {
            int v  = i * 256 + tid;
            int kr = v >> 4;
            int d4 = (v & 15) << 2;
            float4 t = *(const float4*)(Kg + (size_t)kr * DMODEL + d4);
            Ks[(d4 + 0) * KS_STRIDE + kr] = t.x;
            Ks[(d4 + 1) * KS_STRIDE + kr] = t.y;
            Ks[(d4 + 2) * KS_STRIDE + kr] = t.z;
            Ks[(d4 + 3) * KS_STRIDE + kr] = t.w;
            float4 u = *(const float4*)(Vg + (size_t)kr * DMODEL + d4);
            *(float4*)(Vs + kr * VS_STRIDE + d4) = u;
        }
        __syncthreads();

        float accs[8][4];
#pragma unroll
        for (int i = 0; i < 8; i++)
#pragma unroll
            for (int j = 0; j < 4; j++) accs[i][j] = 0.0f;

#pragma unroll 4
        for (int d = 0; d < 64; d++) {
            float4 a0 = *(const float4*)(Qs + d * QS_STRIDE + tq);
            float4 a1 = *(const float4*)(Qs + d * QS_STRIDE + tq + 4);
            float4 bb = *(const float4*)(Ks + d * KS_STRIDE + tk);
            float av[8] = {a0.x, a0.y, a0.z, a0.w, a1.x, a1.y, a1.z, a1.w};
            float bv[4] = {bb.x, bb.y, bb.z, bb.w};
#pragma unroll
            for (int i = 0; i < 8; i++)
#pragma unroll
                for (int j = 0; j < 4; j++) accs[i][j] += av[i] * bv[j];
        }
#pragma unroll
        for (int j = 0; j < 4; j++)
#pragma unroll
            for (int i = 0; i < 8; i++)
                Ps[(tk + j) * PS_STRIDE + tq + i] = accs[i][j];
        __syncthreads();

        if (tid < 128) {
            int qrow  = q0 + tid;
            int limit = qrow - kt * 64;
            if (limit > 63) limit = 63;
            float tmax = -1e30f;
            for (int k = 0; k <= limit; k++)
                tmax = fmaxf(tmax, Ps[k * PS_STRIDE + tid]);
            float mnew  = fmaxf(m, tmax);
            float alpha = __expf(m - mnew);
            float ls = 0.0f;
#pragma unroll 4
            for (int k = 0; k < 64; k++) {
                float p = (k <= limit) ? __expf(Ps[k * PS_STRIDE + tid] - mnew) : 0.0f;
                Ps[k * PS_STRIDE + tid] = p;
                ls += p;
            }
            l = l * alpha + ls;
            m = mnew;
            rowAux[tid] = alpha;
        }
        __syncthreads();

#pragma unroll
        for (int i = 0; i < 8; i++) {
            float al = rowAux[tq + i];
#pragma unroll
            for (int j = 0; j < 4; j++) acc_o[i][j] *= al;
        }
#pragma unroll 4
        for (int kk = 0; kk < 64; kk++) {
            float4 vv = *(const float4*)(Vs + kk * VS_STRIDE + tk);
#pragma unroll
            for (int i = 0; i < 8; i++) {
                float p = Ps[kk * PS_STRIDE + tq + i];
                acc_o[i][0] += p * vv.x;
                acc_o[i][1] += p * vv.y;
                acc_o[i][2] += p * vv.z;
                acc_o[i][3] += p * vv.w;
            }
        }
    }

    __syncthreads();
    if (tid < 128) rowAux[tid] = 1.0f / l;
    __syncthreads();

    float* Og = O + (size_t)(b * TSEQ + q0) * DMODEL + h * DHEAD;
#pragma unroll
    for (int i = 0; i < 8; i++) {
        float inv = rowAux[tq + i];
        float4 r;
        r.x = acc_o[i][0] * inv;
        r.y = acc_o[i][1] * inv;
        r.z = acc_o[i][2] * inv;
        r.w = acc_o[i][3] * inv;
        *(float4*)(Og + (size_t)(tq + i) * DMODEL + tk) = r;
    }
}

// ---------------------------------------------------------------------------
extern "C" void kernel_launch(void* const* d_in, const int* in_sizes, int n_in,
                              void* d_out, int out_size)
{
    (void)in_sizes; (void)n_in; (void)out_size;
    const float* query = (const float*)d_in[0];
    const float* key_  = (const float*)d_in[1];
    const float* value = (const float*)d_in[2];
    const float* q_w   = (const float*)d_in[3];
    const float* q_b   = (const float*)d_in[4];
    const float* k_w   = (const float*)d_in[5];
    const float* k_b   = (const float*)d_in[6];
    const float* v_w   = (const float*)d_in[7];
    const float* v_b   = (const float*)d_in[8];
    const float* o_w   = (const float*)d_in[9];
    const float* o_b   = (const float*)d_in[10];
    float* out = (float*)d_out;

    float *qp, *kp, *vp, *ap;
    cudaGetSymbolAddress((void**)&qp, g_q);
    cudaGetSymbolAddress((void**)&kp, g_k);
    cudaGetSymbolAddress((void**)&vp, g_v);
    cudaGetSymbolAddress((void**)&ap, g_attn);

    cudaFuncSetAttribute(attn_kernel,
                         cudaFuncAttributeMaxDynamicSharedMemorySize,
                         ATTN_SMEM_BYTES);

    dim3 ggrid(DMODEL / 128, MROWS / 128);   // (8, 32)
    gemm_mma_kernel<<<ggrid, 256>>>(query, q_w, q_b, qp);
    gemm_mma_kernel<<<ggrid, 256>>>(key_,  k_w, k_b, kp);
    gemm_mma_kernel<<<ggrid, 256>>>(value, v_w, v_b, vp);

    attn_kernel<<<dim3(TSEQ / 128, NHEAD, BSZ), 256, ATTN_SMEM_BYTES>>>(qp, kp, vp, ap);

    gemm_mma_kernel<<<ggrid, 256>>>(ap, o_w, o_b, out);
}

// round 8
// speedup vs baseline: 2.5232x; 1.0762x over previous
#include <cuda_runtime.h>
#include <math.h>
#include <stdint.h>

#define BSZ   2
#define TSEQ  2048
#define DMODEL 1024
#define NHEAD 16
#define DHEAD 64
#define MROWS (BSZ * TSEQ)   // 4096

// Scratch (allocation-free rule: __device__ globals)
__device__ float g_q[MROWS * DMODEL];
__device__ float g_k[MROWS * DMODEL];
__device__ float g_v[MROWS * DMODEL];
__device__ float g_attn[MROWS * DMODEL];

__device__ __forceinline__ float tf32r(float x) {
    asm("cvt.rna.tf32.f32 %0, %0;" : "+f"(x));
    return x;
}

__device__ __forceinline__ float ex2(float x) {
    float r;
    asm("ex2.approx.ftz.f32 %0, %1;" : "=f"(r) : "f"(x));
    return r;
}

__device__ __forceinline__ void mma_tf32(float* c, const uint32_t* a, const uint32_t* b) {
    asm volatile(
        "mma.sync.aligned.m16n8k8.row.col.f32.tf32.tf32.f32 "
        "{%0,%1,%2,%3}, {%4,%5,%6,%7}, {%8,%9}, {%0,%1,%2,%3};"
        : "+f"(c[0]), "+f"(c[1]), "+f"(c[2]), "+f"(c[3])
        : "r"(a[0]), "r"(a[1]), "r"(a[2]), "r"(a[3]), "r"(b[0]), "r"(b[1]));
}

// ===========================================================================
// Tensor-core GEMM via legacy mma.sync (tf32): C = A[M,K] @ W[N,K]^T + bias
// (unchanged from round 7: ~74us each)
// ===========================================================================
__global__ __launch_bounds__(256) void gemm_mma_kernel(
    const float* __restrict__ A, const float* __restrict__ W,
    const float* __restrict__ bias, float* __restrict__ C)
{
    __shared__ float As[128][36];
    __shared__ float Ws[128][36];

    const int tid = threadIdx.x;
    const int wid = tid >> 5;
    const int lid = tid & 31;
    const int bn  = blockIdx.x * 128;
    const int bm  = blockIdx.y * 128;
    const int wm  = (wid >> 2) * 64;
    const int wn  = (wid & 3) * 32;
    const int g   = lid >> 2;
    const int tig = lid & 3;

    float acc[4][4][4];
#pragma unroll
    for (int mi = 0; mi < 4; mi++)
#pragma unroll
        for (int ni = 0; ni < 4; ni++)
#pragma unroll
            for (int r = 0; r < 4; r++) acc[mi][ni][r] = 0.0f;

    for (int k0 = 0; k0 < DMODEL; k0 += 32) {
        if (k0) __syncthreads();
#pragma unroll
        for (int i = 0; i < 4; i++) {
            int v   = i * 256 + tid;
            int row = v >> 3;
            int c4  = (v & 7) << 2;
            float4 a = *(const float4*)(A + (size_t)(bm + row) * DMODEL + k0 + c4);
            a.x = tf32r(a.x); a.y = tf32r(a.y); a.z = tf32r(a.z); a.w = tf32r(a.w);
            *(float4*)&As[row][c4] = a;
            float4 w = *(const float4*)(W + (size_t)(bn + row) * DMODEL + k0 + c4);
            w.x = tf32r(w.x); w.y = tf32r(w.y); w.z = tf32r(w.z); w.w = tf32r(w.w);
            *(float4*)&Ws[row][c4] = w;
        }
        __syncthreads();

#pragma unroll
        for (int kk = 0; kk < 32; kk += 8) {
            uint32_t af[4][4], bf[4][2];
#pragma unroll
            for (int mi = 0; mi < 4; mi++) {
                const int m = wm + mi * 16 + g;
                af[mi][0] = __float_as_uint(As[m    ][kk + tig    ]);
                af[mi][1] = __float_as_uint(As[m + 8][kk + tig    ]);
                af[mi][2] = __float_as_uint(As[m    ][kk + tig + 4]);
                af[mi][3] = __float_as_uint(As[m + 8][kk + tig + 4]);
            }
#pragma unroll
            for (int ni = 0; ni < 4; ni++) {
                const int n = wn + ni * 8 + g;
                bf[ni][0] = __float_as_uint(Ws[n][kk + tig    ]);
                bf[ni][1] = __float_as_uint(Ws[n][kk + tig + 4]);
            }
#pragma unroll
            for (int mi = 0; mi < 4; mi++)
#pragma unroll
                for (int ni = 0; ni < 4; ni++)
                    mma_tf32(acc[mi][ni], af[mi], bf[ni]);
        }
    }

#pragma unroll
    for (int ni = 0; ni < 4; ni++) {
        const int n = bn + wn + ni * 8 + 2 * tig;
        const float b0 = bias[n], b1 = bias[n + 1];
#pragma unroll
        for (int mi = 0; mi < 4; mi++) {
            const int m0 = bm + wm + mi * 16 + g;
            float2 lo = make_float2(acc[mi][ni][0] + b0, acc[mi][ni][1] + b1);
            float2 hi = make_float2(acc[mi][ni][2] + b0, acc[mi][ni][3] + b1);
            *(float2*)(C + (size_t)m0 * DMODEL + n)       = lo;
            *(float2*)(C + (size_t)(m0 + 8) * DMODEL + n) = hi;
        }
    }
}

// ===========================================================================
// Causal flash attention with tensor-core MMAs (tf32).
// Grid (T/128, H, B), 256 threads = 8 warps (2 m-split x 4 n-split).
// Per 64-key tile: S = Q@K^T via MMA -> Ps smem -> online softmax (all 256
// threads, 2 per row) -> O += P@V via MMA with persistent accumulator.
// Pitch-68 smem: all fragment LDS conflict-free (bank = 4g+tig).
// ===========================================================================
#define APITCH 68
#define AQS_OFF 0        // Qs[128][68]
#define AKS_OFF 8704     // Ks[64][68]  natural [k][d]
#define AVS_OFF 13056    // Vs[64][68]  transposed [d][k]
#define APS_OFF 17408    // Ps[128][68] scores then probabilities
#define AAUX_OFF 26112   // 128 floats: alpha / 1/l
#define ATTN_SMEM_BYTES ((26112 + 128) * 4)   // 104,960 B

__global__ __launch_bounds__(256) void attn_mma_kernel(
    const float* __restrict__ Q, const float* __restrict__ K,
    const float* __restrict__ V, float* __restrict__ O)
{
    extern __shared__ float sm[];
    float* Qs  = sm + AQS_OFF;
    float* Ks  = sm + AKS_OFF;
    float* Vs  = sm + AVS_OFF;
    float* Ps  = sm + APS_OFF;
    float* aux = sm + AAUX_OFF;

    const int qt  = blockIdx.x;
    const int h   = blockIdx.y;
    const int b   = blockIdx.z;
    const int tid = threadIdx.x;
    const int wid = tid >> 5;
    const int lid = tid & 31;
    const int g   = lid >> 2;
    const int tig = lid & 3;
    const int wm  = (wid >> 2) * 64;    // 0 / 64
    const int wn  = (wid & 3) * 16;     // 0/16/32/48
    const int q0  = qt * 128;

    // Q tile [128][64] natural, scaled by 1/sqrt(64)*log2(e), tf32-rounded.
    const float SC = 0.18033688011f;
    const float* Qg = Q + (size_t)(b * TSEQ + q0) * DMODEL + h * DHEAD;
#pragma unroll
    for (int i = 0; i < 8; i++) {
        int v  = i * 256 + tid;
        int qr = v >> 4;
        int d4 = (v & 15) << 2;
        float4 t = *(const float4*)(Qg + (size_t)qr * DMODEL + d4);
        t.x = tf32r(t.x * SC); t.y = tf32r(t.y * SC);
        t.z = tf32r(t.z * SC); t.w = tf32r(t.w * SC);
        *(float4*)&Qs[qr * APITCH + d4] = t;
    }

    float acc[4][2][4];
#pragma unroll
    for (int mi = 0; mi < 4; mi++)
#pragma unroll
        for (int ni = 0; ni < 2; ni++)
#pragma unroll
            for (int r = 0; r < 4; r++) acc[mi][ni][r] = 0.0f;

    const int srow = tid >> 1;          // softmax row (0..127)
    const int shalf = tid & 1;          // which 32-col half
    float mrow = -1e30f, lrow = 0.0f;

    const int n_kt = 2 * qt + 2;
    for (int kt = 0; kt < n_kt; kt++) {
        __syncthreads();
        // K natural [k][d]; V transposed [d][k].
        const float* Kg = K + (size_t)(b * TSEQ + kt * 64) * DMODEL + h * DHEAD;
        const float* Vg = V + (size_t)(b * TSEQ + kt * 64) * DMODEL + h * DHEAD;
#pragma unroll
        for (int i = 0; i < 4; i++) {
            int v  = i * 256 + tid;
            int kr = v >> 4;
            int d4 = (v & 15) << 2;
            float4 t = *(const float4*)(Kg + (size_t)kr * DMODEL + d4);
            t.x = tf32r(t.x); t.y = tf32r(t.y); t.z = tf32r(t.z); t.w = tf32r(t.w);
            *(float4*)&Ks[kr * APITCH + d4] = t;
            float4 u = *(const float4*)(Vg + (size_t)kr * DMODEL + d4);
            Vs[(d4 + 0) * APITCH + kr] = tf32r(u.x);
            Vs[(d4 + 1) * APITCH + kr] = tf32r(u.y);
            Vs[(d4 + 2) * APITCH + kr] = tf32r(u.z);
            Vs[(d4 + 3) * APITCH + kr] = tf32r(u.w);
        }
        __syncthreads();

        // ---- S = Q @ K^T ----
        float sacc[4][2][4];
#pragma unroll
        for (int mi = 0; mi < 4; mi++)
#pragma unroll
            for (int ni = 0; ni < 2; ni++)
#pragma unroll
                for (int r = 0; r < 4; r++) sacc[mi][ni][r] = 0.0f;

#pragma unroll
        for (int kk = 0; kk < 64; kk += 8) {
            uint32_t af[4][4], bf[2][2];
#pragma unroll
            for (int mi = 0; mi < 4; mi++) {
                const int m = wm + mi * 16 + g;
                af[mi][0] = __float_as_uint(Qs[m * APITCH + kk + tig]);
                af[mi][1] = __float_as_uint(Qs[(m + 8) * APITCH + kk + tig]);
                af[mi][2] = __float_as_uint(Qs[m * APITCH + kk + tig + 4]);
                af[mi][3] = __float_as_uint(Qs[(m + 8) * APITCH + kk + tig + 4]);
            }
#pragma unroll
            for (int ni = 0; ni < 2; ni++) {
                const int n = wn + ni * 8 + g;
                bf[ni][0] = __float_as_uint(Ks[n * APITCH + kk + tig]);
                bf[ni][1] = __float_as_uint(Ks[n * APITCH + kk + tig + 4]);
            }
#pragma unroll
            for (int mi = 0; mi < 4; mi++)
#pragma unroll
                for (int ni = 0; ni < 2; ni++)
                    mma_tf32(sacc[mi][ni], af[mi], bf[ni]);
        }
        // Store S to Ps[q][k].
#pragma unroll
        for (int mi = 0; mi < 4; mi++) {
            const int m0 = wm + mi * 16 + g;
#pragma unroll
            for (int ni = 0; ni < 2; ni++) {
                const int n = wn + ni * 8 + 2 * tig;
                *(float2*)&Ps[m0 * APITCH + n] =
                    make_float2(sacc[mi][ni][0], sacc[mi][ni][1]);
                *(float2*)&Ps[(m0 + 8) * APITCH + n] =
                    make_float2(sacc[mi][ni][2], sacc[mi][ni][3]);
            }
        }
        __syncthreads();

        // ---- online softmax: 2 threads per row, 32 cols each ----
        {
            const int limit = (q0 + srow) - kt * 64;   // valid keys k <= limit
            const int kbase = shalf * 32;
            float* prow = Ps + srow * APITCH + kbase;
            float4 vals[8];
            float pmax = -1e30f;
#pragma unroll
            for (int j = 0; j < 8; j++) {
                float4 t = *(const float4*)(prow + 4 * j);
                int k = kbase + 4 * j;
                if (k + 0 > limit) t.x = -1e30f;
                if (k + 1 > limit) t.y = -1e30f;
                if (k + 2 > limit) t.z = -1e30f;
                if (k + 3 > limit) t.w = -1e30f;
                vals[j] = t;
                pmax = fmaxf(pmax, fmaxf(fmaxf(t.x, t.y), fmaxf(t.z, t.w)));
            }
            pmax = fmaxf(pmax, __shfl_xor_sync(0xffffffffu, pmax, 1));
            float mnew  = fmaxf(mrow, pmax);
            float alpha = ex2(mrow - mnew);
            float ls = 0.0f;
#pragma unroll
            for (int j = 0; j < 8; j++) {
                float4 t = vals[j];
                t.x = tf32r(ex2(t.x - mnew));
                t.y = tf32r(ex2(t.y - mnew));
                t.z = tf32r(ex2(t.z - mnew));
                t.w = tf32r(ex2(t.w - mnew));
                ls += (t.x + t.y) + (t.z + t.w);
                *(float4*)(prow + 4 * j) = t;
            }
            ls += __shfl_xor_sync(0xffffffffu, ls, 1);
            lrow = lrow * alpha + ls;
            mrow = mnew;
            if (shalf == 0) aux[srow] = alpha;
        }
        __syncthreads();

        // ---- rescale + O += P @ V ----
#pragma unroll
        for (int mi = 0; mi < 4; mi++) {
            const int m0 = wm + mi * 16 + g;
            const float a0 = aux[m0], a1 = aux[m0 + 8];
#pragma unroll
            for (int ni = 0; ni < 2; ni++) {
                acc[mi][ni][0] *= a0; acc[mi][ni][1] *= a0;
                acc[mi][ni][2] *= a1; acc[mi][ni][3] *= a1;
            }
        }
#pragma unroll
        for (int kk = 0; kk < 64; kk += 8) {
            uint32_t af[4][4], bf[2][2];
#pragma unroll
            for (int mi = 0; mi < 4; mi++) {
                const int m = wm + mi * 16 + g;
                af[mi][0] = __float_as_uint(Ps[m * APITCH + kk + tig]);
                af[mi][1] = __float_as_uint(Ps[(m + 8) * APITCH + kk + tig]);
                af[mi][2] = __float_as_uint(Ps[m * APITCH + kk + tig + 4]);
                af[mi][3] = __float_as_uint(Ps[(m + 8) * APITCH + kk + tig + 4]);
            }
#pragma unroll
            for (int ni = 0; ni < 2; ni++) {
                const int n = wn + ni * 8 + g;     // d dimension
                bf[ni][0] = __float_as_uint(Vs[n * APITCH + kk + tig]);
                bf[ni][1] = __float_as_uint(Vs[n * APITCH + kk + tig + 4]);
            }
#pragma unroll
            for (int mi = 0; mi < 4; mi++)
#pragma unroll
                for (int ni = 0; ni < 2; ni++)
                    mma_tf32(acc[mi][ni], af[mi], bf[ni]);
        }
    }

    // Final normalize + store.
    __syncthreads();
    if (shalf == 0) aux[srow] = 1.0f / lrow;
    __syncthreads();

    float* Og = O + (size_t)(b * TSEQ + q0) * DMODEL + h * DHEAD;
#pragma unroll
    for (int mi = 0; mi < 4; mi++) {
        const int m0 = wm + mi * 16 + g;
        const float i0 = aux[m0], i1 = aux[m0 + 8];
#pragma unroll
        for (int ni = 0; ni < 2; ni++) {
            const int n = wn + ni * 8 + 2 * tig;
            *(float2*)(Og + (size_t)m0 * DMODEL + n) =
                make_float2(acc[mi][ni][0] * i0, acc[mi][ni][1] * i0);
            *(float2*)(Og + (size_t)(m0 + 8) * DMODEL + n) =
                make_float2(acc[mi][ni][2] * i1, acc[mi][ni][3] * i1);
        }
    }
}

// ---------------------------------------------------------------------------
extern "C" void kernel_launch(void* const* d_in, const int* in_sizes, int n_in,
                              void* d_out, int out_size)
{
    (void)in_sizes; (void)n_in; (void)out_size;
    const float* query = (const float*)d_in[0];
    const float* key_  = (const float*)d_in[1];
    const float* value = (const float*)d_in[2];
    const float* q_w   = (const float*)d_in[3];
    const float* q_b   = (const float*)d_in[4];
    const float* k_w   = (const float*)d_in[5];
    const float* k_b   = (const float*)d_in[6];
    const float* v_w   = (const float*)d_in[7];
    const float* v_b   = (const float*)d_in[8];
    const float* o_w   = (const float*)d_in[9];
    const float* o_b   = (const float*)d_in[10];
    float* out = (float*)d_out;

    float *qp, *kp, *vp, *ap;
    cudaGetSymbolAddress((void**)&qp, g_q);
    cudaGetSymbolAddress((void**)&kp, g_k);
    cudaGetSymbolAddress((void**)&vp, g_v);
    cudaGetSymbolAddress((void**)&ap, g_attn);

    cudaFuncSetAttribute(attn_mma_kernel,
                         cudaFuncAttributeMaxDynamicSharedMemorySize,
                         ATTN_SMEM_BYTES);

    dim3 ggrid(DMODEL / 128, MROWS / 128);   // (8, 32)
    gemm_mma_kernel<<<ggrid, 256>>>(query, q_w, q_b, qp);
    gemm_mma_kernel<<<ggrid, 256>>>(key_,  k_w, k_b, kp);
    gemm_mma_kernel<<<ggrid, 256>>>(value, v_w, v_b, vp);

    attn_mma_kernel<<<dim3(TSEQ / 128, NHEAD, BSZ), 256, ATTN_SMEM_BYTES>>>(qp, kp, vp, ap);

    gemm_mma_kernel<<<ggrid, 256>>>(ap, o_w, o_b, out);
}

// round 10
// speedup vs baseline: 2.7349x; 1.0839x over previous
#include <cuda_runtime.h>
#include <math.h>
#include <stdint.h>

#define BSZ   2
#define TSEQ  2048
#define DMODEL 1024
#define NHEAD 16
#define DHEAD 64
#define MROWS (BSZ * TSEQ)   // 4096

// Scratch (allocation-free rule: __device__ globals)
__device__ float g_q[MROWS * DMODEL];
__device__ float g_k[MROWS * DMODEL];
__device__ float g_v[MROWS * DMODEL];
__device__ float g_attn[MROWS * DMODEL];

__device__ __forceinline__ float tf32r(float x) {
    asm("cvt.rna.tf32.f32 %0, %0;" : "+f"(x));
    return x;
}

__device__ __forceinline__ float ex2(float x) {
    float r;
    asm("ex2.approx.ftz.f32 %0, %1;" : "=f"(r) : "f"(x));
    return r;
}

__device__ __forceinline__ void mma_tf32(float* c, const uint32_t* a, const uint32_t* b) {
    asm volatile(
        "mma.sync.aligned.m16n8k8.row.col.f32.tf32.tf32.f32 "
        "{%0,%1,%2,%3}, {%4,%5,%6,%7}, {%8,%9}, {%0,%1,%2,%3};"
        : "+f"(c[0]), "+f"(c[1]), "+f"(c[2]), "+f"(c[3])
        : "r"(a[0]), "r"(a[1]), "r"(a[2]), "r"(a[3]), "r"(b[0]), "r"(b[1]));
}

// ===========================================================================
// Tensor-core GEMM via legacy mma.sync (tf32): C = A[M,K] @ W[N,K]^T + bias
// (unchanged from round 7: ~74us each)
// ===========================================================================
__global__ __launch_bounds__(256) void gemm_mma_kernel(
    const float* __restrict__ A, const float* __restrict__ W,
    const float* __restrict__ bias, float* __restrict__ C)
{
    __shared__ float As[128][36];
    __shared__ float Ws[128][36];

    const int tid = threadIdx.x;
    const int wid = tid >> 5;
    const int lid = tid & 31;
    const int bn  = blockIdx.x * 128;
    const int bm  = blockIdx.y * 128;
    const int wm  = (wid >> 2) * 64;
    const int wn  = (wid & 3) * 32;
    const int g   = lid >> 2;
    const int tig = lid & 3;

    float acc[4][4][4];
#pragma unroll
    for (int mi = 0; mi < 4; mi++)
#pragma unroll
        for (int ni = 0; ni < 4; ni++)
#pragma unroll
            for (int r = 0; r < 4; r++) acc[mi][ni][r] = 0.0f;

    for (int k0 = 0; k0 < DMODEL; k0 += 32) {
        if (k0) __syncthreads();
#pragma unroll
        for (int i = 0; i < 4; i++) {
            int v   = i * 256 + tid;
            int row = v >> 3;
            int c4  = (v & 7) << 2;
            float4 a = *(const float4*)(A + (size_t)(bm + row) * DMODEL + k0 + c4);
            a.x = tf32r(a.x); a.y = tf32r(a.y); a.z = tf32r(a.z); a.w = tf32r(a.w);
            *(float4*)&As[row][c4] = a;
            float4 w = *(const float4*)(W + (size_t)(bn + row) * DMODEL + k0 + c4);
            w.x = tf32r(w.x); w.y = tf32r(w.y); w.z = tf32r(w.z); w.w = tf32r(w.w);
            *(float4*)&Ws[row][c4] = w;
        }
        __syncthreads();

#pragma unroll
        for (int kk = 0; kk < 32; kk += 8) {
            uint32_t af[4][4], bf[4][2];
#pragma unroll
            for (int mi = 0; mi < 4; mi++) {
                const int m = wm + mi * 16 + g;
                af[mi][0] = __float_as_uint(As[m    ][kk + tig    ]);
                af[mi][1] = __float_as_uint(As[m + 8][kk + tig    ]);
                af[mi][2] = __float_as_uint(As[m    ][kk + tig + 4]);
                af[mi][3] = __float_as_uint(As[m + 8][kk + tig + 4]);
            }
#pragma unroll
            for (int ni = 0; ni < 4; ni++) {
                const int n = wn + ni * 8 + g;
                bf[ni][0] = __float_as_uint(Ws[n][kk + tig    ]);
                bf[ni][1] = __float_as_uint(Ws[n][kk + tig + 4]);
            }
#pragma unroll
            for (int mi = 0; mi < 4; mi++)
#pragma unroll
                for (int ni = 0; ni < 4; ni++)
                    mma_tf32(acc[mi][ni], af[mi], bf[ni]);
        }
    }

#pragma unroll
    for (int ni = 0; ni < 4; ni++) {
        const int n = bn + wn + ni * 8 + 2 * tig;
        const float b0 = bias[n], b1 = bias[n + 1];
#pragma unroll
        for (int mi = 0; mi < 4; mi++) {
            const int m0 = bm + wm + mi * 16 + g;
            float2 lo = make_float2(acc[mi][ni][0] + b0, acc[mi][ni][1] + b1);
            float2 hi = make_float2(acc[mi][ni][2] + b0, acc[mi][ni][3] + b1);
            *(float2*)(C + (size_t)m0 * DMODEL + n)       = lo;
            *(float2*)(C + (size_t)(m0 + 8) * DMODEL + n) = hi;
        }
    }
}

// ===========================================================================
// Causal flash attention, FA2-style: warps split over M only.
// Grid (T/128, H, B), 256 threads = 8 warps x 16 query rows.
// Each warp computes the full 64-key strip for its rows: S fragments stay in
// registers, softmax via quad shfl (rows g, g+8 live in lanes 4g..4g+3),
// P round-trips through a WARP-PRIVATE smem slab (syncwarp only).
// Block barriers: 2 per tile (K/V staging).
// SMEM: Ks 64 rows + Vs 64 rows + Ps 128 rows, pitch 68 = 256*68 floats.
// ===========================================================================
#define FPITCH 68
#define FKS_OFF 0                 // Ks[64][68]  natural [k][d]
#define FVS_OFF (64 * FPITCH)     // Vs[64][68]  transposed [d][k]
#define FPS_OFF (128 * FPITCH)    // Ps[128][68] Q staging, then per-warp P slabs
#define FATTN_SMEM_BYTES ((256 * FPITCH) * 4)   // 69,632 B

__global__ __launch_bounds__(256) void attn_fa2_kernel(
    const float* __restrict__ Q, const float* __restrict__ K,
    const float* __restrict__ V, float* __restrict__ O)
{
    extern __shared__ float sm[];
    float* Ks = sm + FKS_OFF;
    float* Vs = sm + FVS_OFF;
    float* Ps = sm + FPS_OFF;

    const int qt  = blockIdx.x;
    const int h   = blockIdx.y;
    const int b   = blockIdx.z;
    const int tid = threadIdx.x;
    const int wid = tid >> 5;
    const int lid = tid & 31;
    const int g   = lid >> 2;
    const int tig = lid & 3;
    const int wm  = wid * 16;          // this warp's 16 query rows
    const int q0  = qt * 128;

    // Stage this warp's Q rows into its Ps slab (scaled by 1/8 * log2e), then
    // extract persistent A-fragments. Warp-private -> syncwarp only.
    const float SC = 0.18033688011f;   // (1/sqrt(64)) * log2(e)
    const float* Qg = Q + (size_t)(b * TSEQ + q0 + wm) * DMODEL + h * DHEAD;
#pragma unroll
    for (int i = 0; i < 8; i++) {
        int v   = i * 32 + lid;        // 0..255
        int row = v >> 4;              // 0..15
        int c4  = (v & 15) << 2;       // 0..60
        float4 t = *(const float4*)(Qg + (size_t)row * DMODEL + c4);
        t.x = tf32r(t.x * SC); t.y = tf32r(t.y * SC);
        t.z = tf32r(t.z * SC); t.w = tf32r(t.w * SC);
        *(float4*)&Ps[(wm + row) * FPITCH + c4] = t;
    }
    __syncwarp();

    uint32_t qf[8][4];
#pragma unroll
    for (int kk = 0; kk < 8; kk++) {
        qf[kk][0] = __float_as_uint(Ps[(wm + g) * FPITCH + kk * 8 + tig]);
        qf[kk][1] = __float_as_uint(Ps[(wm + g + 8) * FPITCH + kk * 8 + tig]);
        qf[kk][2] = __float_as_uint(Ps[(wm + g) * FPITCH + kk * 8 + tig + 4]);
        qf[kk][3] = __float_as_uint(Ps[(wm + g + 8) * FPITCH + kk * 8 + tig + 4]);
    }
    __syncwarp();

    float acc[8][4];
#pragma unroll
    for (int ni = 0; ni < 8; ni++)
#pragma unroll
        for (int r = 0; r < 4; r++) acc[ni][r] = 0.0f;

    float m0 = -1e30f, m1 = -1e30f, l0 = 0.0f, l1 = 0.0f;
    const int row0 = q0 + wm + g;      // global row for c0/c1
    // row1 = row0 + 8

    const int n_kt = 2 * qt + 2;
    for (int kt = 0; kt < n_kt; kt++) {
        __syncthreads();   // everyone done reading Ks/Vs of previous tile
        const float* Kg = K + (size_t)(b * TSEQ + kt * 64) * DMODEL + h * DHEAD;
        const float* Vg = V + (size_t)(b * TSEQ + kt * 64) * DMODEL + h * DHEAD;
#pragma unroll
        for (int i = 0; i < 4; i++) {
            int v  = i * 256 + tid;
            int kr = v >> 4;
            int d4 = (v & 15) << 2;
            float4 t = *(const float4*)(Kg + (size_t)kr * DMODEL + d4);
            t.x = tf32r(t.x); t.y = tf32r(t.y); t.z = tf32r(t.z); t.w = tf32r(t.w);
            *(float4*)&Ks[kr * FPITCH + d4] = t;
            float4 u = *(const float4*)(Vg + (size_t)kr * DMODEL + d4);
            Vs[(d4 + 0) * FPITCH + kr] = tf32r(u.x);
            Vs[(d4 + 1) * FPITCH + kr] = tf32r(u.y);
            Vs[(d4 + 2) * FPITCH + kr] = tf32r(u.z);
            Vs[(d4 + 3) * FPITCH + kr] = tf32r(u.w);
        }
        __syncthreads();

        // ---- S = Q @ K^T (registers) ----
        float sacc[8][4];
#pragma unroll
        for (int ni = 0; ni < 8; ni++)
#pragma unroll
            for (int r = 0; r < 4; r++) sacc[ni][r] = 0.0f;

#pragma unroll
        for (int kk = 0; kk < 8; kk++) {
#pragma unroll
            for (int ni = 0; ni < 8; ni++) {
                uint32_t bf[2];
                bf[0] = __float_as_uint(Ks[(ni * 8 + g) * FPITCH + kk * 8 + tig]);
                bf[1] = __float_as_uint(Ks[(ni * 8 + g) * FPITCH + kk * 8 + tig + 4]);
                mma_tf32(sacc[ni], qf[kk], bf);
            }
        }

        // ---- causal mask (registers) ----
        const int lim0 = row0 - kt * 64;       // valid keys: col <= lim0
        const int lim1 = lim0 + 8;
#pragma unroll
        for (int ni = 0; ni < 8; ni++) {
            const int c0 = ni * 8 + 2 * tig;
            const int c1 = c0 + 1;
            if (c0 > lim0) sacc[ni][0] = -1e30f;
            if (c1 > lim0) sacc[ni][1] = -1e30f;
            if (c0 > lim1) sacc[ni][2] = -1e30f;
            if (c1 > lim1) sacc[ni][3] = -1e30f;
        }

        // ---- online softmax (registers + quad shfl) ----
        float mx0 = -1e30f, mx1 = -1e30f;
#pragma unroll
        for (int ni = 0; ni < 8; ni++) {
            mx0 = fmaxf(mx0, fmaxf(sacc[ni][0], sacc[ni][1]));
            mx1 = fmaxf(mx1, fmaxf(sacc[ni][2], sacc[ni][3]));
        }
        mx0 = fmaxf(mx0, __shfl_xor_sync(0xffffffffu, mx0, 1));
        mx0 = fmaxf(mx0, __shfl_xor_sync(0xffffffffu, mx0, 2));
        mx1 = fmaxf(mx1, __shfl_xor_sync(0xffffffffu, mx1, 1));
        mx1 = fmaxf(mx1, __shfl_xor_sync(0xffffffffu, mx1, 2));

        const float mn0 = fmaxf(m0, mx0);
        const float mn1 = fmaxf(m1, mx1);
        const float a0 = ex2(m0 - mn0);
        const float a1 = ex2(m1 - mn1);
        float ls0 = 0.0f, ls1 = 0.0f;
#pragma unroll
        for (int ni = 0; ni < 8; ni++) {
            float p0 = tf32r(ex2(sacc[ni][0] - mn0));
            float p1 = tf32r(ex2(sacc[ni][1] - mn0));
            float p2 = tf32r(ex2(sacc[ni][2] - mn1));
            float p3 = tf32r(ex2(sacc[ni][3] - mn1));
            sacc[ni][0] = p0; sacc[ni][1] = p1;
            sacc[ni][2] = p2; sacc[ni][3] = p3;
            ls0 += p0 + p1;
            ls1 += p2 + p3;
        }
        ls0 += __shfl_xor_sync(0xffffffffu, ls0, 1);
        ls0 += __shfl_xor_sync(0xffffffffu, ls0, 2);
        ls1 += __shfl_xor_sync(0xffffffffu, ls1, 1);
        ls1 += __shfl_xor_sync(0xffffffffu, ls1, 2);
        l0 = l0 * a0 + ls0;
        l1 = l1 * a1 + ls1;
        m0 = mn0; m1 = mn1;

        // rescale running O
#pragma unroll
        for (int ni = 0; ni < 8; ni++) {
            acc[ni][0] *= a0; acc[ni][1] *= a0;
            acc[ni][2] *= a1; acc[ni][3] *= a1;
        }

        // ---- P -> warp-private slab -> A fragments ----
#pragma unroll
        for (int ni = 0; ni < 8; ni++) {
            *(float2*)&Ps[(wm + g) * FPITCH + ni * 8 + 2 * tig] =
                make_float2(sacc[ni][0], sacc[ni][1]);
            *(float2*)&Ps[(wm + g + 8) * FPITCH + ni * 8 + 2 * tig] =
                make_float2(sacc[ni][2], sacc[ni][3]);
        }
        __syncwarp();

        // ---- O += P @ V ----
#pragma unroll
        for (int kk = 0; kk < 8; kk++) {
            uint32_t af[4];
            af[0] = __float_as_uint(Ps[(wm + g) * FPITCH + kk * 8 + tig]);
            af[1] = __float_as_uint(Ps[(wm + g + 8) * FPITCH + kk * 8 + tig]);
            af[2] = __float_as_uint(Ps[(wm + g) * FPITCH + kk * 8 + tig + 4]);
            af[3] = __float_as_uint(Ps[(wm + g + 8) * FPITCH + kk * 8 + tig + 4]);
#pragma unroll
            for (int ni = 0; ni < 8; ni++) {
                uint32_t bf[2];
                bf[0] = __float_as_uint(Vs[(ni * 8 + g) * FPITCH + kk * 8 + tig]);
                bf[1] = __float_as_uint(Vs[(ni * 8 + g) * FPITCH + kk * 8 + tig + 4]);
                mma_tf32(acc[ni], af, bf);
            }
        }
        __syncwarp();   // slab reads done before next tile overwrites
    }

    // ---- normalize + store ----
    const float inv0 = 1.0f / l0;
    const float inv1 = 1.0f / l1;
    float* Og = O + (size_t)(b * TSEQ + q0 + wm) * DMODEL + h * DHEAD;
#pragma unroll
    for (int ni = 0; ni < 8; ni++) {
        const int n = ni * 8 + 2 * tig;
        *(float2*)(Og + (size_t)g * DMODEL + n) =
            make_float2(acc[ni][0] * inv0, acc[ni][1] * inv0);
        *(float2*)(Og + (size_t)(g + 8) * DMODEL + n) =
            make_float2(acc[ni][2] * inv1, acc[ni][3] * inv1);
    }
}

// ---------------------------------------------------------------------------
extern "C" void kernel_launch(void* const* d_in, const int* in_sizes, int n_in,
                              void* d_out, int out_size)
{
    (void)in_sizes; (void)n_in; (void)out_size;
    const float* query = (const float*)d_in[0];
    const float* key_  = (const float*)d_in[1];
    const float* value = (const float*)d_in[2];
    const float* q_w   = (const float*)d_in[3];
    const float* q_b   = (const float*)d_in[4];
    const float* k_w   = (const float*)d_in[5];
    const float* k_b   = (const float*)d_in[6];
    const float* v_w   = (const float*)d_in[7];
    const float* v_b   = (const float*)d_in[8];
    const float* o_w   = (const float*)d_in[9];
    const float* o_b   = (const float*)d_in[10];
    float* out = (float*)d_out;

    float *qp, *kp, *vp, *ap;
    cudaGetSymbolAddress((void**)&qp, g_q);
    cudaGetSymbolAddress((void**)&kp, g_k);
    cudaGetSymbolAddress((void**)&vp, g_v);
    cudaGetSymbolAddress((void**)&ap, g_attn);

    cudaFuncSetAttribute(attn_fa2_kernel,
                         cudaFuncAttributeMaxDynamicSharedMemorySize,
                         FATTN_SMEM_BYTES);

    dim3 ggrid(DMODEL / 128, MROWS / 128);   // (8, 32)
    gemm_mma_kernel<<<ggrid, 256>>>(query, q_w, q_b, qp);
    gemm_mma_kernel<<<ggrid, 256>>>(key_,  k_w, k_b, kp);
    gemm_mma_kernel<<<ggrid, 256>>>(value, v_w, v_b, vp);

    attn_fa2_kernel<<<dim3(TSEQ / 128, NHEAD, BSZ), 256, FATTN_SMEM_BYTES>>>(qp, kp, vp, ap);

    gemm_mma_kernel<<<ggrid, 256>>>(ap, o_w, o_b, out);
}

// round 11
// speedup vs baseline: 4.2749x; 1.5631x over previous
#include <cuda_runtime.h>
#include <math.h>
#include <stdint.h>

#define BSZ   2
#define TSEQ  2048
#define DMODEL 1024
#define NHEAD 16
#define DHEAD 64
#define MROWS (BSZ * TSEQ)   // 4096

// Scratch (allocation-free rule: __device__ globals)
__device__ float g_q[MROWS * DMODEL];
__device__ float g_k[MROWS * DMODEL];
__device__ float g_v[MROWS * DMODEL];
__device__ float g_attn[MROWS * DMODEL];

__device__ __forceinline__ float tf32r(float x) {
    asm("cvt.rna.tf32.f32 %0, %0;" : "+f"(x));
    return x;
}

__device__ __forceinline__ float ex2(float x) {
    float r;
    asm("ex2.approx.ftz.f32 %0, %1;" : "=f"(r) : "f"(x));
    return r;
}

__device__ __forceinline__ void mma_tf32(float* c, const uint32_t* a, const uint32_t* b) {
    asm volatile(
        "mma.sync.aligned.m16n8k8.row.col.f32.tf32.tf32.f32 "
        "{%0,%1,%2,%3}, {%4,%5,%6,%7}, {%8,%9}, {%0,%1,%2,%3};"
        : "+f"(c[0]), "+f"(c[1]), "+f"(c[2]), "+f"(c[3])
        : "r"(a[0]), "r"(a[1]), "r"(a[2]), "r"(a[3]), "r"(b[0]), "r"(b[1]));
}

// ===========================================================================
// Tensor-core GEMM via legacy mma.sync (tf32): C = A[M,K] @ W[N,K]^T + bias
// (unchanged from round 7: ~74us each)
// ===========================================================================
__global__ __launch_bounds__(256) void gemm_mma_kernel(
    const float* __restrict__ A, const float* __restrict__ W,
    const float* __restrict__ bias, float* __restrict__ C)
{
    __shared__ float As[128][36];
    __shared__ float Ws[128][36];

    const int tid = threadIdx.x;
    const int wid = tid >> 5;
    const int lid = tid & 31;
    const int bn  = blockIdx.x * 128;
    const int bm  = blockIdx.y * 128;
    const int wm  = (wid >> 2) * 64;
    const int wn  = (wid & 3) * 32;
    const int g   = lid >> 2;
    const int tig = lid & 3;

    float acc[4][4][4];
#pragma unroll
    for (int mi = 0; mi < 4; mi++)
#pragma unroll
        for (int ni = 0; ni < 4; ni++)
#pragma unroll
            for (int r = 0; r < 4; r++) acc[mi][ni][r] = 0.0f;

    for (int k0 = 0; k0 < DMODEL; k0 += 32) {
        if (k0) __syncthreads();
#pragma unroll
        for (int i = 0; i < 4; i++) {
            int v   = i * 256 + tid;
            int row = v >> 3;
            int c4  = (v & 7) << 2;
            float4 a = *(const float4*)(A + (size_t)(bm + row) * DMODEL + k0 + c4);
            a.x = tf32r(a.x); a.y = tf32r(a.y); a.z = tf32r(a.z); a.w = tf32r(a.w);
            *(float4*)&As[row][c4] = a;
            float4 w = *(const float4*)(W + (size_t)(bn + row) * DMODEL + k0 + c4);
            w.x = tf32r(w.x); w.y = tf32r(w.y); w.z = tf32r(w.z); w.w = tf32r(w.w);
            *(float4*)&Ws[row][c4] = w;
        }
        __syncthreads();

#pragma unroll
        for (int kk = 0; kk < 32; kk += 8) {
            uint32_t af[4][4], bf[4][2];
#pragma unroll
            for (int mi = 0; mi < 4; mi++) {
                const int m = wm + mi * 16 + g;
                af[mi][0] = __float_as_uint(As[m    ][kk + tig    ]);
                af[mi][1] = __float_as_uint(As[m + 8][kk + tig    ]);
                af[mi][2] = __float_as_uint(As[m    ][kk + tig + 4]);
                af[mi][3] = __float_as_uint(As[m + 8][kk + tig + 4]);
            }
#pragma unroll
            for (int ni = 0; ni < 4; ni++) {
                const int n = wn + ni * 8 + g;
                bf[ni][0] = __float_as_uint(Ws[n][kk + tig    ]);
                bf[ni][1] = __float_as_uint(Ws[n][kk + tig + 4]);
            }
#pragma unroll
            for (int mi = 0; mi < 4; mi++)
#pragma unroll
                for (int ni = 0; ni < 4; ni++)
                    mma_tf32(acc[mi][ni], af[mi], bf[ni]);
        }
    }

#pragma unroll
    for (int ni = 0; ni < 4; ni++) {
        const int n = bn + wn + ni * 8 + 2 * tig;
        const float b0 = bias[n], b1 = bias[n + 1];
#pragma unroll
        for (int mi = 0; mi < 4; mi++) {
            const int m0 = bm + wm + mi * 16 + g;
            float2 lo = make_float2(acc[mi][ni][0] + b0, acc[mi][ni][1] + b1);
            float2 hi = make_float2(acc[mi][ni][2] + b0, acc[mi][ni][3] + b1);
            *(float2*)(C + (size_t)m0 * DMODEL + n)       = lo;
            *(float2*)(C + (size_t)(m0 + 8) * DMODEL + n) = hi;
        }
    }
}

// ===========================================================================
// Causal flash attention, FA2-style, 2 CTAs/SM.
// Grid (T/128, H, B), 256 threads = 8 warps x 16 query rows.
// Q lives in its own smem region (reloaded as fragments per tile) so regs
// stay <= 128 -> 2 CTAs/SM. S fragments in registers, softmax via quad shfl,
// P through a warp-private slab (syncwarp only).
// SMEM: Qs[128] + Ks[64] + Vs[64] + Ps[128] rows, pitch 68.
// ===========================================================================
#define FPITCH 68
#define FQS_OFF 0                  // Qs[128][68]  natural [q][d], pre-scaled
#define FKS_OFF (128 * FPITCH)     // Ks[64][68]   natural [k][d]
#define FVS_OFF (192 * FPITCH)     // Vs[64][68]   transposed [d][k]
#define FPS_OFF (256 * FPITCH)     // Ps[128][68]  per-warp P slabs
#define FATTN_SMEM_BYTES ((384 * FPITCH) * 4)   // 104,448 B

__global__ __launch_bounds__(256, 2) void attn_fa2_kernel(
    const float* __restrict__ Q, const float* __restrict__ K,
    const float* __restrict__ V, float* __restrict__ O)
{
    extern __shared__ float sm[];
    float* Qs = sm + FQS_OFF;
    float* Ks = sm + FKS_OFF;
    float* Vs = sm + FVS_OFF;
    float* Ps = sm + FPS_OFF;

    const int qt  = blockIdx.x;
    const int h   = blockIdx.y;
    const int b   = blockIdx.z;
    const int tid = threadIdx.x;
    const int wid = tid >> 5;
    const int lid = tid & 31;
    const int g   = lid >> 2;
    const int tig = lid & 3;
    const int wm  = wid * 16;          // this warp's 16 query rows
    const int q0  = qt * 128;

    // Stage this warp's Q rows into Qs (scaled by 1/8 * log2e). Warp-private.
    const float SC = 0.18033688011f;   // (1/sqrt(64)) * log2(e)
    const float* Qg = Q + (size_t)(b * TSEQ + q0 + wm) * DMODEL + h * DHEAD;
#pragma unroll
    for (int i = 0; i < 8; i++) {
        int v   = i * 32 + lid;        // 0..255
        int row = v >> 4;              // 0..15
        int c4  = (v & 15) << 2;       // 0..60
        float4 t = *(const float4*)(Qg + (size_t)row * DMODEL + c4);
        t.x = tf32r(t.x * SC); t.y = tf32r(t.y * SC);
        t.z = tf32r(t.z * SC); t.w = tf32r(t.w * SC);
        *(float4*)&Qs[(wm + row) * FPITCH + c4] = t;
    }
    __syncwarp();

    float acc[8][4];
#pragma unroll
    for (int ni = 0; ni < 8; ni++)
#pragma unroll
        for (int r = 0; r < 4; r++) acc[ni][r] = 0.0f;

    float m0 = -1e30f, m1 = -1e30f, l0 = 0.0f, l1 = 0.0f;
    const int row0 = q0 + wm + g;      // global row for c0/c1 (row1 = row0+8)

    const int n_kt = 2 * qt + 2;
    for (int kt = 0; kt < n_kt; kt++) {
        __syncthreads();   // everyone done reading Ks/Vs of previous tile
        const float* Kg = K + (size_t)(b * TSEQ + kt * 64) * DMODEL + h * DHEAD;
        const float* Vg = V + (size_t)(b * TSEQ + kt * 64) * DMODEL + h * DHEAD;
#pragma unroll
        for (int i = 0; i < 4; i++) {
            int v  = i * 256 + tid;
            int kr = v >> 4;
            int d4 = (v & 15) << 2;
            float4 t = *(const float4*)(Kg + (size_t)kr * DMODEL + d4);
            t.x = tf32r(t.x); t.y = tf32r(t.y); t.z = tf32r(t.z); t.w = tf32r(t.w);
            *(float4*)&Ks[kr * FPITCH + d4] = t;
            float4 u = *(const float4*)(Vg + (size_t)kr * DMODEL + d4);
            Vs[(d4 + 0) * FPITCH + kr] = tf32r(u.x);
            Vs[(d4 + 1) * FPITCH + kr] = tf32r(u.y);
            Vs[(d4 + 2) * FPITCH + kr] = tf32r(u.z);
            Vs[(d4 + 3) * FPITCH + kr] = tf32r(u.w);
        }
        __syncthreads();

        // ---- S = Q @ K^T (C-fragments in registers, Q frags from smem) ----
        float sacc[8][4];
#pragma unroll
        for (int ni = 0; ni < 8; ni++)
#pragma unroll
            for (int r = 0; r < 4; r++) sacc[ni][r] = 0.0f;

#pragma unroll
        for (int kk = 0; kk < 8; kk++) {
            uint32_t af[4];
            af[0] = __float_as_uint(Qs[(wm + g) * FPITCH + kk * 8 + tig]);
            af[1] = __float_as_uint(Qs[(wm + g + 8) * FPITCH + kk * 8 + tig]);
            af[2] = __float_as_uint(Qs[(wm + g) * FPITCH + kk * 8 + tig + 4]);
            af[3] = __float_as_uint(Qs[(wm + g + 8) * FPITCH + kk * 8 + tig + 4]);
#pragma unroll
            for (int ni = 0; ni < 8; ni++) {
                uint32_t bf[2];
                bf[0] = __float_as_uint(Ks[(ni * 8 + g) * FPITCH + kk * 8 + tig]);
                bf[1] = __float_as_uint(Ks[(ni * 8 + g) * FPITCH + kk * 8 + tig + 4]);
                mma_tf32(sacc[ni], af, bf);
            }
        }

        // ---- causal mask (registers) ----
        const int lim0 = row0 - kt * 64;       // valid keys: col <= lim0
        const int lim1 = lim0 + 8;
#pragma unroll
        for (int ni = 0; ni < 8; ni++) {
            const int c0 = ni * 8 + 2 * tig;
            const int c1 = c0 + 1;
            if (c0 > lim0) sacc[ni][0] = -1e30f;
            if (c1 > lim0) sacc[ni][1] = -1e30f;
            if (c0 > lim1) sacc[ni][2] = -1e30f;
            if (c1 > lim1) sacc[ni][3] = -1e30f;
        }

        // ---- online softmax (registers + quad shfl) ----
        float mx0 = -1e30f, mx1 = -1e30f;
#pragma unroll
        for (int ni = 0; ni < 8; ni++) {
            mx0 = fmaxf(mx0, fmaxf(sacc[ni][0], sacc[ni][1]));
            mx1 = fmaxf(mx1, fmaxf(sacc[ni][2], sacc[ni][3]));
        }
        mx0 = fmaxf(mx0, __shfl_xor_sync(0xffffffffu, mx0, 1));
        mx0 = fmaxf(mx0, __shfl_xor_sync(0xffffffffu, mx0, 2));
        mx1 = fmaxf(mx1, __shfl_xor_sync(0xffffffffu, mx1, 1));
        mx1 = fmaxf(mx1, __shfl_xor_sync(0xffffffffu, mx1, 2));

        const float mn0 = fmaxf(m0, mx0);
        const float mn1 = fmaxf(m1, mx1);
        const float a0 = ex2(m0 - mn0);
        const float a1 = ex2(m1 - mn1);
        float ls0 = 0.0f, ls1 = 0.0f;
#pragma unroll
        for (int ni = 0; ni < 8; ni++) {
            float p0 = tf32r(ex2(sacc[ni][0] - mn0));
            float p1 = tf32r(ex2(sacc[ni][1] - mn0));
            float p2 = tf32r(ex2(sacc[ni][2] - mn1));
            float p3 = tf32r(ex2(sacc[ni][3] - mn1));
            sacc[ni][0] = p0; sacc[ni][1] = p1;
            sacc[ni][2] = p2; sacc[ni][3] = p3;
            ls0 += p0 + p1;
            ls1 += p2 + p3;
        }
        ls0 += __shfl_xor_sync(0xffffffffu, ls0, 1);
        ls0 += __shfl_xor_sync(0xffffffffu, ls0, 2);
        ls1 += __shfl_xor_sync(0xffffffffu, ls1, 1);
        ls1 += __shfl_xor_sync(0xffffffffu, ls1, 2);
        l0 = l0 * a0 + ls0;
        l1 = l1 * a1 + ls1;
        m0 = mn0; m1 = mn1;

        // rescale running O
#pragma unroll
        for (int ni = 0; ni < 8; ni++) {
            acc[ni][0] *= a0; acc[ni][1] *= a0;
            acc[ni][2] *= a1; acc[ni][3] *= a1;
        }

        // ---- P -> warp-private slab -> A fragments ----
#pragma unroll
        for (int ni = 0; ni < 8; ni++) {
            *(float2*)&Ps[(wm + g) * FPITCH + ni * 8 + 2 * tig] =
                make_float2(sacc[ni][0], sacc[ni][1]);
            *(float2*)&Ps[(wm + g + 8) * FPITCH + ni * 8 + 2 * tig] =
                make_float2(sacc[ni][2], sacc[ni][3]);
        }
        __syncwarp();

        // ---- O += P @ V ----
#pragma unroll
        for (int kk = 0; kk < 8; kk++) {
            uint32_t af[4];
            af[0] = __float_as_uint(Ps[(wm + g) * FPITCH + kk * 8 + tig]);
            af[1] = __float_as_uint(Ps[(wm + g + 8) * FPITCH + kk * 8 + tig]);
            af[2] = __float_as_uint(Ps[(wm + g) * FPITCH + kk * 8 + tig + 4]);
            af[3] = __float_as_uint(Ps[(wm + g + 8) * FPITCH + kk * 8 + tig + 4]);
#pragma unroll
            for (int ni = 0; ni < 8; ni++) {
                uint32_t bf[2];
                bf[0] = __float_as_uint(Vs[(ni * 8 + g) * FPITCH + kk * 8 + tig]);
                bf[1] = __float_as_uint(Vs[(ni * 8 + g) * FPITCH + kk * 8 + tig + 4]);
                mma_tf32(acc[ni], af, bf);
            }
        }
        __syncwarp();   // slab reads done before next tile overwrites
    }

    // ---- normalize + store ----
    const float inv0 = 1.0f / l0;
    const float inv1 = 1.0f / l1;
    float* Og = O + (size_t)(b * TSEQ + q0 + wm) * DMODEL + h * DHEAD;
#pragma unroll
    for (int ni = 0; ni < 8; ni++) {
        const int n = ni * 8 + 2 * tig;
        *(float2*)(Og + (size_t)g * DMODEL + n) =
            make_float2(acc[ni][0] * inv0, acc[ni][1] * inv0);
        *(float2*)(Og + (size_t)(g + 8) * DMODEL + n) =
            make_float2(acc[ni][2] * inv1, acc[ni][3] * inv1);
    }
}

// ---------------------------------------------------------------------------
extern "C" void kernel_launch(void* const* d_in, const int* in_sizes, int n_in,
                              void* d_out, int out_size)
{
    (void)in_sizes; (void)n_in; (void)out_size;
    const float* query = (const float*)d_in[0];
    const float* key_  = (const float*)d_in[1];
    const float* value = (const float*)d_in[2];
    const float* q_w   = (const float*)d_in[3];
    const float* q_b   = (const float*)d_in[4];
    const float* k_w   = (const float*)d_in[5];
    const float* k_b   = (const float*)d_in[6];
    const float* v_w   = (const float*)d_in[7];
    const float* v_b   = (const float*)d_in[8];
    const float* o_w   = (const float*)d_in[9];
    const float* o_b   = (const float*)d_in[10];
    float* out = (float*)d_out;

    float *qp, *kp, *vp, *ap;
    cudaGetSymbolAddress((void**)&qp, g_q);
    cudaGetSymbolAddress((void**)&kp, g_k);
    cudaGetSymbolAddress((void**)&vp, g_v);
    cudaGetSymbolAddress((void**)&ap, g_attn);

    cudaFuncSetAttribute(attn_fa2_kernel,
                         cudaFuncAttributeMaxDynamicSharedMemorySize,
                         FATTN_SMEM_BYTES);

    dim3 ggrid(DMODEL / 128, MROWS / 128);   // (8, 32)
    gemm_mma_kernel<<<ggrid, 256>>>(query, q_w, q_b, qp);
    gemm_mma_kernel<<<ggrid, 256>>>(key_,  k_w, k_b, kp);
    gemm_mma_kernel<<<ggrid, 256>>>(value, v_w, v_b, vp);

    attn_fa2_kernel<<<dim3(TSEQ / 128, NHEAD, BSZ), 256, FATTN_SMEM_BYTES>>>(qp, kp, vp, ap);

    gemm_mma_kernel<<<ggrid, 256>>>(ap, o_w, o_b, out);
}